// round 3
// baseline (speedup 1.0000x reference)
#include <cuda_runtime.h>
#include <math.h>

#define NROWS 16384      // 2 * 8*32*32
#define NCODE 4096
#define KDIM  256
#define SPB   8192       // spatial per batch
#define ZTOT  4194304    // 2*256*8192

// output layout: concatenation of reference outputs, float32
#define OFF_LOSS   0ull
#define OFF_ZQ     1ull
#define OFF_PERP   4194305ull
#define OFF_OH     4194306ull
#define OFF_IDX    71303170ull
#define OFF_ZOUT   71319554ull
#define OFF_EMA    75513858ull

// scratch
__device__ float  g_Anorm[NROWS];
__device__ float  g_Snorm[NCODE];
__device__ float  g_pd[NROWS * 32];
__device__ int    g_pj[NROWS * 32];
__device__ int    g_idx[NROWS];
__device__ int    g_cnt[NCODE];
__device__ double g_losspart[4096];

// ---------------------------------------------------------------- init
__global__ void k_init() {
    int t = blockIdx.x * 256 + threadIdx.x;
    if (t < NCODE) g_cnt[t] = 0;
}

// ---------------------------------------------------------------- row norms ||z_n||^2
__global__ void k_rownorm(const float* __restrict__ z) {
    int n = blockIdx.x * 256 + threadIdx.x;
    int b = n >> 13, s = n & (SPB - 1);
    const float* p = z + (size_t)b * (KDIM * SPB) + s;
    float a = 0.f;
    #pragma unroll 8
    for (int c = 0; c < KDIM; c++) {
        float v = p[(size_t)c * SPB];
        a = __fmaf_rn(v, v, a);
    }
    g_Anorm[n] = a;
}

// ---------------------------------------------------------------- code norms ||e_j||^2
__global__ void k_codenorm(const float* __restrict__ E) {
    int w = blockIdx.x * 8 + (threadIdx.x >> 5);
    int lane = threadIdx.x & 31;
    const float* p = E + (size_t)w * KDIM;
    float a = 0.f;
    #pragma unroll
    for (int i = 0; i < 8; i++) {
        float v = p[lane + i * 32];
        a = __fmaf_rn(v, v, a);
    }
    #pragma unroll
    for (int off = 16; off > 0; off >>= 1)
        a += __shfl_xor_sync(0xffffffffu, a, off);
    if (lane == 0) g_Snorm[w] = a;
}

// ---------------------------------------------------------------- GEMM + per-tile argmin
// D[n][j] = fl( fl(An + Sj) - 2*dot(z_n, e_j) ), argmin_j with first-index ties.
#define BM 128
#define BN 128
#define BK 8

__global__ __launch_bounds__(256, 2)
void k_gemm_argmin(const float* __restrict__ z, const float* __restrict__ E) {
    __shared__ float As[BK][BM];
    __shared__ float Bs[BK][BN];
    __shared__ float RedD[BM][16];
    __shared__ int   RedJ[BM][16];

    const int bn = blockIdx.x;      // 0..31  (column tiles of 128 codes)
    const int bm = blockIdx.y;      // 0..127 (row tiles of 128 rows)
    const int tid = threadIdx.x;
    const int tx = tid & 15, ty = tid >> 4;

    const int n0 = bm * BM;
    const int b  = n0 >> 13;
    const int s0 = n0 & (SPB - 1);
    const float* Ab = z + (size_t)b * (KDIM * SPB) + s0;   // (nl,k) -> Ab[k*SPB + nl]
    const float* Bb = E + (size_t)bn * BN * KDIM;          // (jl,k) -> Bb[jl*KDIM + k]

    const int a_nl = (tid & 31) * 4;   // 0..124
    const int a_k  = tid >> 5;         // 0..7
    const int b_jl = tid >> 1;         // 0..127
    const int b_k  = (tid & 1) * 4;    // 0 or 4

    float acc[8][8];
    #pragma unroll
    for (int i = 0; i < 8; i++)
        #pragma unroll
        for (int j = 0; j < 8; j++) acc[i][j] = 0.f;

    for (int k0 = 0; k0 < KDIM; k0 += BK) {
        float4 av = *(const float4*)(Ab + (size_t)(k0 + a_k) * SPB + a_nl);
        float4 bv = *(const float4*)(Bb + (size_t)b_jl * KDIM + k0 + b_k);
        __syncthreads();
        *(float4*)&As[a_k][a_nl] = av;
        Bs[b_k + 0][b_jl] = bv.x;
        Bs[b_k + 1][b_jl] = bv.y;
        Bs[b_k + 2][b_jl] = bv.z;
        Bs[b_k + 3][b_jl] = bv.w;
        __syncthreads();
        #pragma unroll
        for (int k = 0; k < BK; k++) {
            float4 a0 = *(float4*)&As[k][ty * 8];
            float4 a1 = *(float4*)&As[k][ty * 8 + 4];
            float4 b0 = *(float4*)&Bs[k][tx * 8];
            float4 b1 = *(float4*)&Bs[k][tx * 8 + 4];
            float ar[8] = {a0.x, a0.y, a0.z, a0.w, a1.x, a1.y, a1.z, a1.w};
            float br[8] = {b0.x, b0.y, b0.z, b0.w, b1.x, b1.y, b1.z, b1.w};
            #pragma unroll
            for (int i = 0; i < 8; i++)
                #pragma unroll
                for (int j = 0; j < 8; j++)
                    acc[i][j] = __fmaf_rn(ar[i], br[j], acc[i][j]);
        }
    }

    // epilogue: d = (An + Sj) - 2*acc ; per-row argmin over this tile's 128 codes
    float an[8];
    #pragma unroll
    for (int ri = 0; ri < 8; ri++) an[ri] = g_Anorm[n0 + ty * 8 + ri];
    float sj[8];
    #pragma unroll
    for (int ci = 0; ci < 8; ci++) sj[ci] = g_Snorm[bn * BN + tx * 8 + ci];

    #pragma unroll
    for (int ri = 0; ri < 8; ri++) {
        float bd = __int_as_float(0x7f800000);  // +inf
        int bj = 0;
        #pragma unroll
        for (int ci = 0; ci < 8; ci++) {       // ascending j -> first-index ties
            float t = __fadd_rn(an[ri], sj[ci]);
            float d = __fmaf_rn(-2.0f, acc[ri][ci], t);
            if (d < bd) { bd = d; bj = bn * BN + tx * 8 + ci; }
        }
        RedD[ty * 8 + ri][tx] = bd;
        RedJ[ty * 8 + ri][tx] = bj;
    }
    __syncthreads();
    if (tid < BM) {
        float bd = RedD[tid][0];
        int   bj = RedJ[tid][0];
        #pragma unroll
        for (int t = 1; t < 16; t++) {
            float d = RedD[tid][t]; int j = RedJ[tid][t];
            if (d < bd || (d == bd && j < bj)) { bd = d; bj = j; }
        }
        int n = n0 + tid;
        g_pd[(size_t)n * 32 + bn] = bd;
        g_pj[(size_t)n * 32 + bn] = bj;
    }
}

// ---------------------------------------------------------------- reduce 32 tile-partials per row
__global__ void k_finalize_argmin(float* __restrict__ out) {
    int n = blockIdx.x * 256 + threadIdx.x;
    const float* pd = g_pd + (size_t)n * 32;
    const int*   pj = g_pj + (size_t)n * 32;
    float bd = pd[0]; int bj = pj[0];
    #pragma unroll
    for (int t = 1; t < 32; t++) {
        float d = pd[t]; int j = pj[t];
        if (d < bd || (d == bd && j < bj)) { bd = d; bj = j; }
    }
    g_idx[n] = bj;
    out[OFF_IDX + n] = (float)bj;
    atomicAdd(&g_cnt[bj], 1);
}

// ---------------------------------------------------------------- one-hot scatter
__global__ void k_scatter(float* __restrict__ out) {
    int n = blockIdx.x * 256 + threadIdx.x;
    out[OFF_OH + (size_t)n * NCODE + (size_t)g_idx[n]] = 1.0f;
}

// ---------------------------------------------------------------- z_q (straight-through), z_out copy, loss partials
__global__ void k_zq_loss(const float* __restrict__ z, const float* __restrict__ E,
                          float* __restrict__ out) {
    size_t i4 = (size_t)blockIdx.x * 256 + threadIdx.x;   // 4096*256 threads
    size_t i = i4 * 4;
    int bb = (int)(i >> 21);
    int rem = (int)(i & 2097151u);
    int c = rem >> 13;
    int s = rem & (SPB - 1);
    float4 zp = *(const float4*)(z + i);
    int nbase = bb * SPB + s;
    float zv[4] = {zp.x, zp.y, zp.z, zp.w};
    double ls = 0.0;
    float q[4];
    #pragma unroll
    for (int u = 0; u < 4; u++) {
        int idx = g_idx[nbase + u];
        float e = E[(size_t)idx * KDIM + c];
        float d1 = __fsub_rn(e, zv[u]);         // z_q - zp
        q[u] = __fadd_rn(zv[u], d1);            // straight-through: zp + (z_q - zp)
        float sq = __fmul_rn(d1, d1);
        ls += (double)sq;
    }
    // scalar stores (offsets not 16B-aligned)
    #pragma unroll
    for (int u = 0; u < 4; u++) {
        out[OFF_ZQ + i + u]   = q[u];
        out[OFF_ZOUT + i + u] = zv[u];
    }
    // deterministic block reduction of loss partial
    #pragma unroll
    for (int off = 16; off > 0; off >>= 1)
        ls += __shfl_down_sync(0xffffffffu, ls, off);
    __shared__ double wsum[8];
    int t = threadIdx.x;
    if ((t & 31) == 0) wsum[t >> 5] = ls;
    __syncthreads();
    if (t == 0) {
        double ssum = 0.0;
        #pragma unroll
        for (int w = 0; w < 8; w++) ssum += wsum[w];
        g_losspart[blockIdx.x] = ssum;
    }
}

// ---------------------------------------------------------------- ema update
__global__ void k_ema(const float* __restrict__ E, const float* __restrict__ ema,
                      float* __restrict__ out) {
    int i = blockIdx.x * 256 + threadIdx.x;   // 1,048,576 elements
    float a = __fmul_rn(0.25f, ema[i]);
    float bq = __fmul_rn(0.75f, E[i]);
    out[OFF_EMA + i] = __fadd_rn(a, bq);
}

// ---------------------------------------------------------------- scalars: loss, perplexity
__global__ void k_scalars(float* __restrict__ out) {
    __shared__ double sd[256];
    int t = threadIdx.x;
    double a = 0.0;
    for (int i = t; i < 4096; i += 256) a += g_losspart[i];
    sd[t] = a;
    __syncthreads();
    for (int off = 128; off > 0; off >>= 1) {
        if (t < off) sd[t] += sd[t + off];
        __syncthreads();
    }
    if (t == 0) {
        double m = sd[0] / (double)ZTOT;
        float mf = (float)m;
        out[OFF_LOSS] = __fadd_rn(mf, __fmul_rn(0.25f, mf));
    }
    __syncthreads();
    double h = 0.0;
    for (int j = t; j < NCODE; j += 256) {
        double e = (double)g_cnt[j] / (double)NROWS;
        h += e * log(e + 1e-10);
    }
    sd[t] = h;
    __syncthreads();
    for (int off = 128; off > 0; off >>= 1) {
        if (t < off) sd[t] += sd[t + off];
        __syncthreads();
    }
    if (t == 0) out[OFF_PERP] = (float)exp(-sd[0]);
}

// ---------------------------------------------------------------- launch
extern "C" void kernel_launch(void* const* d_in, const int* in_sizes, int n_in,
                              void* d_out, int out_size) {
    const float* z   = (const float*)d_in[0];
    const float* E   = (const float*)d_in[1];
    const float* ema = (const float*)d_in[2];
    float* out = (float*)d_out;

    k_init<<<16, 256>>>();
    k_rownorm<<<NROWS / 256, 256>>>(z);
    k_codenorm<<<NCODE / 8, 256>>>(E);

    dim3 grid(NCODE / BN, NROWS / BM);   // (32, 128)
    k_gemm_argmin<<<grid, 256>>>(z, E);

    k_finalize_argmin<<<NROWS / 256, 256>>>(out);

    cudaMemsetAsync(out + OFF_OH, 0, (size_t)NROWS * NCODE * sizeof(float), 0);
    k_scatter<<<NROWS / 256, 256>>>(out);

    k_zq_loss<<<4096, 256>>>(z, E, out);
    k_ema<<<(NCODE * KDIM) / 256, 256>>>(E, ema, out);
    k_scalars<<<1, 256>>>(out);
}

// round 7
// speedup vs baseline: 1.2497x; 1.2497x over previous
#include <cuda_runtime.h>
#include <math.h>
#include <stdint.h>

#define NROWS 16384      // 2 * 8*32*32
#define NCODE 4096
#define KDIM  256
#define SPB   8192       // spatial per batch
#define ZTOT  4194304    // 2*256*8192

// output layout: concatenation of reference outputs, float32
#define OFF_LOSS   0ull
#define OFF_ZQ     1ull
#define OFF_PERP   4194305ull
#define OFF_OH     4194306ull
#define OFF_IDX    71303170ull
#define OFF_ZOUT   71319554ull
#define OFF_EMA    75513858ull

// ---------------- scratch ----------------
__device__ float  g_Anorm[NROWS];
__device__ float  g_Snorm[NCODE];
__device__ float  g_pd[NROWS * 32];
__device__ int    g_pj[NROWS * 32];
__device__ int    g_idx[NROWS];
__device__ int    g_cnt[NCODE];
__device__ double g_losspart[4096];
__device__ __align__(16) float g_Et[(size_t)KDIM * NCODE];   // E transposed: [k][j]

// ---------------- small helpers ----------------
__device__ __forceinline__ void ffma2(unsigned long long& acc, unsigned long long a,
                                      unsigned long long b) {
    asm("fma.rn.f32x2 %0, %1, %2, %0;" : "+l"(acc) : "l"(a), "l"(b));
}
__device__ __forceinline__ unsigned long long dup2(float x) {
    unsigned long long r;
    asm("mov.b64 %0, {%1, %1};" : "=l"(r) : "f"(x));
    return r;
}
__device__ __forceinline__ void unpack2(unsigned long long v, float& lo, float& hi) {
    asm("mov.b64 {%0, %1}, %2;" : "=f"(lo), "=f"(hi) : "l"(v));
}
__device__ __forceinline__ uint32_t smem_u32(const void* p) {
    uint32_t a;
    asm("{ .reg .u64 t; cvta.to.shared.u64 t, %1; cvt.u32.u64 %0, t; }" : "=r"(a) : "l"(p));
    return a;
}
#define CP_ASYNC16(dst, src) \
    asm volatile("cp.async.cg.shared.global [%0], [%1], 16;" :: "r"(dst), "l"(src) : "memory")
#define CP_COMMIT() asm volatile("cp.async.commit_group;" ::: "memory")
#define CP_WAIT0()  asm volatile("cp.async.wait_group 0;" ::: "memory")

// ---------------------------------------------------------------- init
__global__ void k_init() {
    int t = blockIdx.x * 256 + threadIdx.x;
    if (t < NCODE) g_cnt[t] = 0;
}

// ---------------------------------------------------------------- row norms ||z_n||^2
__global__ void k_rownorm(const float* __restrict__ z) {
    int n = blockIdx.x * 256 + threadIdx.x;
    int b = n >> 13, s = n & (SPB - 1);
    const float* p = z + (size_t)b * (KDIM * SPB) + s;
    float a = 0.f;
    #pragma unroll 8
    for (int c = 0; c < KDIM; c++) {
        float v = p[(size_t)c * SPB];
        a = __fmaf_rn(v, v, a);
    }
    g_Anorm[n] = a;
}

// ---------------------------------------------------------------- code norms ||e_j||^2
__global__ void k_codenorm(const float* __restrict__ E) {
    int w = blockIdx.x * 8 + (threadIdx.x >> 5);
    int lane = threadIdx.x & 31;
    const float* p = E + (size_t)w * KDIM;
    float a = 0.f;
    #pragma unroll
    for (int i = 0; i < 8; i++) {
        float v = p[lane + i * 32];
        a = __fmaf_rn(v, v, a);
    }
    #pragma unroll
    for (int off = 16; off > 0; off >>= 1)
        a += __shfl_xor_sync(0xffffffffu, a, off);
    if (lane == 0) g_Snorm[w] = a;
}

// ---------------------------------------------------------------- E transpose: [j][k] -> [k][j]
__global__ void k_transposeE(const float* __restrict__ E) {
    __shared__ float tile[32][33];
    int tx = threadIdx.x, ty = threadIdx.y;   // 32 x 8
    int j0 = blockIdx.x * 32, k0 = blockIdx.y * 32;
    #pragma unroll
    for (int r = 0; r < 4; r++)
        tile[ty + r * 8][tx] = E[(size_t)(j0 + ty + r * 8) * KDIM + k0 + tx];
    __syncthreads();
    #pragma unroll
    for (int r = 0; r < 4; r++)
        g_Et[(size_t)(k0 + ty + r * 8) * NCODE + j0 + tx] = tile[tx][ty + r * 8];
}

// ---------------------------------------------------------------- FFMA2 GEMM + argmin
// BM=256, BN=128, BK=16, 256 threads (16x16), per-thread 16x8 (8 f32x2 row-pairs x 8 cols)
#define BM 256
#define BN 128
#define BK 16
#define NSLICE (KDIM / BK)

struct SmemAB {
    float A[2][BK][BM];   // 32 KB
    float B[2][BK][BN];   // 16 KB
};
struct SmemRed {
    float D[BM][16];      // 16 KB
    int   J[BM][16];      // 16 KB
};
union SmemU {
    SmemAB ab;
    SmemRed red;
};

__global__ __launch_bounds__(256, 1)
void k_gemm_argmin(const float* __restrict__ z) {
    __shared__ SmemU sm;

    const int tid = threadIdx.x;
    const int tx = tid & 15;        // N group: cols tx*8..tx*8+7
    const int ty = tid >> 4;        // M group: rows ty*16..ty*16+15
    const int bn = blockIdx.x;      // 0..31
    const int bm = blockIdx.y;      // 0..63
    const int n0 = bm * BM;
    const int j0 = bn * BN;
    const int b  = n0 >> 13;
    const int s0 = n0 & (SPB - 1);

    const float* zb = z + (size_t)b * (KDIM * SPB) + s0;

    const uint32_t sA = smem_u32(&sm.ab.A[0][0][0]);
    const uint32_t sB = smem_u32(&sm.ab.B[0][0][0]);

    // per-thread load assignments (16B chunks)
    const int a_kr0 = tid >> 6;            // chunk = tid + i*256 ; kr = chunk>>6
    const int a_co0 = (tid & 63) * 4;
    const int b_kr0 = tid >> 5;
    const int b_co0 = (tid & 31) * 4;

    // issue slice 0
    {
        #pragma unroll
        for (int i = 0; i < 4; i++) {
            int kr = a_kr0 + i * 4;
            CP_ASYNC16(sA + (uint32_t)(kr * BM + a_co0) * 4,
                       zb + (size_t)kr * SPB + a_co0);
        }
        #pragma unroll
        for (int i = 0; i < 2; i++) {
            int kr = b_kr0 + i * 8;
            CP_ASYNC16(sB + (uint32_t)(kr * BN + b_co0) * 4,
                       g_Et + (size_t)kr * NCODE + j0 + b_co0);
        }
        CP_COMMIT();
    }

    unsigned long long acc[8][8];
    #pragma unroll
    for (int p = 0; p < 8; p++)
        #pragma unroll
        for (int c = 0; c < 8; c++) acc[p][c] = 0ull;

    const int m0 = ty * 16;

    for (int s = 0; s < NSLICE; s++) {
        const int cur = s & 1;
        CP_WAIT0();
        __syncthreads();
        if (s + 1 < NSLICE) {
            const int nxt = (s + 1) & 1;
            const int k0n = (s + 1) * BK;
            #pragma unroll
            for (int i = 0; i < 4; i++) {
                int kr = a_kr0 + i * 4;
                CP_ASYNC16(sA + (uint32_t)((nxt * BK + kr) * BM + a_co0) * 4,
                           zb + (size_t)(k0n + kr) * SPB + a_co0);
            }
            #pragma unroll
            for (int i = 0; i < 2; i++) {
                int kr = b_kr0 + i * 8;
                CP_ASYNC16(sB + (uint32_t)((nxt * BK + kr) * BN + b_co0) * 4,
                           g_Et + (size_t)(k0n + kr) * NCODE + j0 + b_co0);
            }
            CP_COMMIT();
        }
        #pragma unroll
        for (int k = 0; k < BK; k++) {
            // A: 16 consecutive floats as 4x ulonglong2 (pre-paired f32x2)
            const ulonglong2* ap = (const ulonglong2*)&sm.ab.A[cur][k][m0];
            ulonglong2 a01 = ap[0], a23 = ap[1], a45 = ap[2], a67 = ap[3];
            unsigned long long ar[8] = {a01.x, a01.y, a23.x, a23.y,
                                        a45.x, a45.y, a67.x, a67.y};
            const float4* bp = (const float4*)&sm.ab.B[cur][k][tx * 8];
            float4 b0 = bp[0], b1 = bp[1];
            unsigned long long br[8] = {dup2(b0.x), dup2(b0.y), dup2(b0.z), dup2(b0.w),
                                        dup2(b1.x), dup2(b1.y), dup2(b1.z), dup2(b1.w)};
            #pragma unroll
            for (int p = 0; p < 8; p++)
                #pragma unroll
                for (int c = 0; c < 8; c++)
                    ffma2(acc[p][c], ar[p], br[c]);
        }
    }
    __syncthreads();   // done with AB buffers; reuse as reduction space

    // epilogue: d = fl(fl(An+Sj) - 2*acc); per-row argmin over 128 cols, ascending j
    float sj[8];
    #pragma unroll
    for (int c = 0; c < 8; c++) sj[c] = g_Snorm[j0 + tx * 8 + c];

    #pragma unroll
    for (int p = 0; p < 8; p++) {
        int r0 = m0 + 2 * p;
        float an0 = g_Anorm[n0 + r0];
        float an1 = g_Anorm[n0 + r0 + 1];
        float bd0 = __int_as_float(0x7f800000), bd1 = bd0;
        int bj0 = 0, bj1 = 0;
        #pragma unroll
        for (int c = 0; c < 8; c++) {
            float lo, hi;
            unpack2(acc[p][c], lo, hi);
            float t0 = __fadd_rn(an0, sj[c]);
            float t1 = __fadd_rn(an1, sj[c]);
            float d0 = __fmaf_rn(-2.0f, lo, t0);
            float d1 = __fmaf_rn(-2.0f, hi, t1);
            int j = j0 + tx * 8 + c;
            if (d0 < bd0) { bd0 = d0; bj0 = j; }
            if (d1 < bd1) { bd1 = d1; bj1 = j; }
        }
        sm.red.D[r0][tx] = bd0;     sm.red.J[r0][tx] = bj0;
        sm.red.D[r0 + 1][tx] = bd1; sm.red.J[r0 + 1][tx] = bj1;
    }
    __syncthreads();

    // one thread per row reduces 16 partials (lexicographic (d, j))
    {
        int row = tid;
        float bd = sm.red.D[row][0];
        int   bj = sm.red.J[row][0];
        #pragma unroll
        for (int t = 1; t < 16; t++) {
            float d = sm.red.D[row][t]; int j = sm.red.J[row][t];
            if (d < bd || (d == bd && j < bj)) { bd = d; bj = j; }
        }
        int n = n0 + row;
        g_pd[(size_t)n * 32 + bn] = bd;
        g_pj[(size_t)n * 32 + bn] = bj;
    }
}

// ---------------------------------------------------------------- reduce 32 tile-partials per row
__global__ void k_finalize_argmin(float* __restrict__ out) {
    int n = blockIdx.x * 256 + threadIdx.x;
    const float* pd = g_pd + (size_t)n * 32;
    const int*   pj = g_pj + (size_t)n * 32;
    float bd = pd[0]; int bj = pj[0];
    #pragma unroll
    for (int t = 1; t < 32; t++) {
        float d = pd[t]; int j = pj[t];
        if (d < bd || (d == bd && j < bj)) { bd = d; bj = j; }
    }
    g_idx[n] = bj;
    out[OFF_IDX + n] = (float)bj;
    atomicAdd(&g_cnt[bj], 1);
}

// ---------------------------------------------------------------- one-hot scatter
__global__ void k_scatter(float* __restrict__ out) {
    int n = blockIdx.x * 256 + threadIdx.x;
    out[OFF_OH + (size_t)n * NCODE + (size_t)g_idx[n]] = 1.0f;
}

// ---------------------------------------------------------------- z_q (straight-through), z_out, loss
__global__ void k_zq_loss(const float* __restrict__ z, const float* __restrict__ E,
                          float* __restrict__ out) {
    size_t i4 = (size_t)blockIdx.x * 256 + threadIdx.x;
    size_t i = i4 * 4;
    int bb = (int)(i >> 21);
    int rem = (int)(i & 2097151u);
    int c = rem >> 13;
    int s = rem & (SPB - 1);
    float4 zp = *(const float4*)(z + i);
    int nbase = bb * SPB + s;
    float zv[4] = {zp.x, zp.y, zp.z, zp.w};
    double ls = 0.0;
    float q[4];
    #pragma unroll
    for (int u = 0; u < 4; u++) {
        int idx = g_idx[nbase + u];
        float e = E[(size_t)idx * KDIM + c];
        float d1 = __fsub_rn(e, zv[u]);
        q[u] = __fadd_rn(zv[u], d1);
        float sq = __fmul_rn(d1, d1);
        ls += (double)sq;
    }
    #pragma unroll
    for (int u = 0; u < 4; u++) {
        out[OFF_ZQ + i + u]   = q[u];
        out[OFF_ZOUT + i + u] = zv[u];
    }
    #pragma unroll
    for (int off = 16; off > 0; off >>= 1)
        ls += __shfl_down_sync(0xffffffffu, ls, off);
    __shared__ double wsum[8];
    int t = threadIdx.x;
    if ((t & 31) == 0) wsum[t >> 5] = ls;
    __syncthreads();
    if (t == 0) {
        double ssum = 0.0;
        #pragma unroll
        for (int w = 0; w < 8; w++) ssum += wsum[w];
        g_losspart[blockIdx.x] = ssum;
    }
}

// ---------------------------------------------------------------- ema update
__global__ void k_ema(const float* __restrict__ E, const float* __restrict__ ema,
                      float* __restrict__ out) {
    int i = blockIdx.x * 256 + threadIdx.x;
    float a = __fmul_rn(0.25f, ema[i]);
    float bq = __fmul_rn(0.75f, E[i]);
    out[OFF_EMA + i] = __fadd_rn(a, bq);
}

// ---------------------------------------------------------------- scalars
__global__ void k_scalars(float* __restrict__ out) {
    __shared__ double sd[256];
    int t = threadIdx.x;
    double a = 0.0;
    for (int i = t; i < 4096; i += 256) a += g_losspart[i];
    sd[t] = a;
    __syncthreads();
    for (int off = 128; off > 0; off >>= 1) {
        if (t < off) sd[t] += sd[t + off];
        __syncthreads();
    }
    if (t == 0) {
        double m = sd[0] / (double)ZTOT;
        float mf = (float)m;
        out[OFF_LOSS] = __fadd_rn(mf, __fmul_rn(0.25f, mf));
    }
    __syncthreads();
    double h = 0.0;
    for (int j = t; j < NCODE; j += 256) {
        double e = (double)g_cnt[j] / (double)NROWS;
        h += e * log(e + 1e-10);
    }
    sd[t] = h;
    __syncthreads();
    for (int off = 128; off > 0; off >>= 1) {
        if (t < off) sd[t] += sd[t + off];
        __syncthreads();
    }
    if (t == 0) out[OFF_PERP] = (float)exp(-sd[0]);
}

// ---------------------------------------------------------------- launch
extern "C" void kernel_launch(void* const* d_in, const int* in_sizes, int n_in,
                              void* d_out, int out_size) {
    const float* z   = (const float*)d_in[0];
    const float* E   = (const float*)d_in[1];
    const float* ema = (const float*)d_in[2];
    float* out = (float*)d_out;

    k_init<<<16, 256>>>();
    k_rownorm<<<NROWS / 256, 256>>>(z);
    k_codenorm<<<NCODE / 8, 256>>>(E);
    k_transposeE<<<dim3(NCODE / 32, KDIM / 32), dim3(32, 8)>>>(E);

    k_gemm_argmin<<<dim3(NCODE / BN, NROWS / BM), 256>>>(z);

    k_finalize_argmin<<<NROWS / 256, 256>>>(out);

    cudaMemsetAsync(out + OFF_OH, 0, (size_t)NROWS * NCODE * sizeof(float), 0);
    k_scatter<<<NROWS / 256, 256>>>(out);

    k_zq_loss<<<4096, 256>>>(z, E, out);
    k_ema<<<(NCODE * KDIM) / 256, 256>>>(E, ema, out);
    k_scalars<<<1, 256>>>(out);
}

// round 8
// speedup vs baseline: 1.3674x; 1.0942x over previous
#include <cuda_runtime.h>
#include <math.h>
#include <stdint.h>

#define NROWS 16384      // 2 * 8*32*32
#define NCODE 4096
#define KDIM  256
#define SPB   8192       // spatial per batch
#define ZTOT  4194304    // 2*256*8192

// output layout: concatenation of reference outputs, float32
#define OFF_LOSS   0ull
#define OFF_ZQ     1ull
#define OFF_PERP   4194305ull
#define OFF_OH     4194306ull
#define OFF_IDX    71303170ull
#define OFF_ZOUT   71319554ull
#define OFF_EMA    75513858ull

// ---------------- scratch ----------------
__device__ float  g_Anorm[NROWS];
__device__ float  g_Snorm[NCODE];
__device__ float  g_pd[NROWS * 32];
__device__ int    g_pj[NROWS * 32];
__device__ int    g_idx[NROWS];
__device__ int    g_cnt[NCODE];
__device__ double g_losspart[4096];

// tf32-split operands packed in mma.m16n8k8 fragment order.
// A: [mtile 0..1023][kchunk 0..31][lane*4 + {a0,a1,a2,a3}]
// B: [ntile 0..511 ][kchunk 0..31][lane*2 + {b0,b1}]
__device__ __align__(16) float g_Afh[(size_t)1024 * 32 * 128];
__device__ __align__(16) float g_Afl[(size_t)1024 * 32 * 128];
__device__ __align__(16) float g_Bfh[(size_t)512 * 32 * 64];
__device__ __align__(16) float g_Bfl[(size_t)512 * 32 * 64];

// ---------------- helpers ----------------
__device__ __forceinline__ uint32_t smem_u32(const void* p) {
    uint32_t a;
    asm("{ .reg .u64 t; cvta.to.shared.u64 t, %1; cvt.u32.u64 %0, t; }" : "=r"(a) : "l"(p));
    return a;
}
__device__ __forceinline__ float to_tf32f(float v) {
    uint32_t r;
    asm("cvt.rna.tf32.f32 %0, %1;" : "=r"(r) : "f"(v));
    return __uint_as_float(r);
}
#define CP_ASYNC16(dst, src) \
    asm volatile("cp.async.cg.shared.global [%0], [%1], 16;" :: "r"(dst), "l"(src) : "memory")
#define CP_COMMIT() asm volatile("cp.async.commit_group;" ::: "memory")
#define CP_WAIT0()  asm volatile("cp.async.wait_group 0;" ::: "memory")

__device__ __forceinline__ void mma_tf32(float* c, const uint32_t* a, const uint32_t* b) {
    asm volatile("mma.sync.aligned.m16n8k8.row.col.f32.tf32.tf32.f32 "
        "{%0,%1,%2,%3}, {%4,%5,%6,%7}, {%8,%9}, {%0,%1,%2,%3};"
        : "+f"(c[0]), "+f"(c[1]), "+f"(c[2]), "+f"(c[3])
        : "r"(a[0]), "r"(a[1]), "r"(a[2]), "r"(a[3]), "r"(b[0]), "r"(b[1]));
}

// ---------------------------------------------------------------- init
__global__ void k_init() {
    int t = blockIdx.x * 256 + threadIdx.x;
    if (t < NCODE) g_cnt[t] = 0;
}

// ---------------------------------------------------------------- row norms ||z_n||^2
__global__ void k_rownorm(const float* __restrict__ z) {
    int n = blockIdx.x * 256 + threadIdx.x;
    int b = n >> 13, s = n & (SPB - 1);
    const float* p = z + (size_t)b * (KDIM * SPB) + s;
    float a = 0.f;
    #pragma unroll 8
    for (int c = 0; c < KDIM; c++) {
        float v = p[(size_t)c * SPB];
        a = __fmaf_rn(v, v, a);
    }
    g_Anorm[n] = a;
}

// ---------------------------------------------------------------- code norms ||e_j||^2
__global__ void k_codenorm(const float* __restrict__ E) {
    int w = blockIdx.x * 8 + (threadIdx.x >> 5);
    int lane = threadIdx.x & 31;
    const float* p = E + (size_t)w * KDIM;
    float a = 0.f;
    #pragma unroll
    for (int i = 0; i < 8; i++) {
        float v = p[lane + i * 32];
        a = __fmaf_rn(v, v, a);
    }
    #pragma unroll
    for (int off = 16; off > 0; off >>= 1)
        a += __shfl_xor_sync(0xffffffffu, a, off);
    if (lane == 0) g_Snorm[w] = a;
}

// ---------------------------------------------------------------- A fragment pack (z -> tf32 hi/lo)
// thread -> (T, kc, lane): computes a0..a3 for one fragment slot.
__global__ void k_packA(const float* __restrict__ z) {
    int tid = blockIdx.x * 256 + threadIdx.x;   // 1,048,576
    int l  = tid & 31;
    int kc = (tid >> 5) & 31;
    int T  = tid >> 10;                          // mtile 0..1023
    int g = l >> 2, tg = l & 3;
    int m = T * 16;
    int b = m >> 13;
    int s = (m & (SPB - 1)) + g;
    int k = kc * 8 + tg;
    const float* zb = z + ((size_t)b * KDIM * SPB);
    float v0 = zb[(size_t)k * SPB + s];          // a0: (g,   tg)
    float v1 = zb[(size_t)k * SPB + s + 8];      // a1: (g+8, tg)
    float v2 = zb[(size_t)(k + 4) * SPB + s];    // a2: (g,   tg+4)
    float v3 = zb[(size_t)(k + 4) * SPB + s + 8];// a3: (g+8, tg+4)
    float h0 = to_tf32f(v0), h1 = to_tf32f(v1), h2 = to_tf32f(v2), h3 = to_tf32f(v3);
    float4 hi = make_float4(h0, h1, h2, h3);
    float4 lo = make_float4(to_tf32f(__fsub_rn(v0, h0)), to_tf32f(__fsub_rn(v1, h1)),
                            to_tf32f(__fsub_rn(v2, h2)), to_tf32f(__fsub_rn(v3, h3)));
    size_t o = ((size_t)T * 32 + kc) * 128 + l * 4;
    *(float4*)&g_Afh[o] = hi;
    *(float4*)&g_Afl[o] = lo;
}

// ---------------------------------------------------------------- B fragment pack (E -> tf32 hi/lo)
__global__ void k_packB(const float* __restrict__ E) {
    int tid = blockIdx.x * 256 + threadIdx.x;   // 524,288
    int l  = tid & 31;
    int kc = (tid >> 5) & 31;
    int nt = tid >> 10;                          // ntile 0..511
    int g = l >> 2, tg = l & 3;
    int n = nt * 8 + g;
    float v0 = E[(size_t)n * KDIM + kc * 8 + tg];      // b0: (k=tg,   n=g)
    float v1 = E[(size_t)n * KDIM + kc * 8 + tg + 4];  // b1: (k=tg+4, n=g)
    float h0 = to_tf32f(v0), h1 = to_tf32f(v1);
    size_t o = ((size_t)nt * 32 + kc) * 64 + l * 2;
    g_Bfh[o]     = h0;
    g_Bfh[o + 1] = h1;
    g_Bfl[o]     = to_tf32f(__fsub_rn(v0, h0));
    g_Bfl[o + 1] = to_tf32f(__fsub_rn(v1, h1));
}

// ---------------------------------------------------------------- mma GEMM + argmin
// block tile 128x128, K-stage 32 (4 k8-chunks), double buffered.
// smem: [0,512) Snorm slice; [512, 512+2*65536) stages {Ah 16K, Al 16K, Bh 16K, Bl 16K}
#define STAGE_BYTES_M 65536
#define GSMEM (512 + 2 * STAGE_BYTES_M)

__device__ __forceinline__ void copy_stage(char* sm_, int st, int ks, int bm, int bn, int t) {
    uint32_t sb = smem_u32(sm_ + 512 + st * STAGE_BYTES_M);
    #pragma unroll
    for (int i = 0; i < 8; i++) {
        int a = t + i * 256;
        int half = a >> 10, c = a & 1023;
        int mt = c >> 7, kc = (c >> 5) & 3, q = c & 31;
        const float* src = (half ? g_Afl : g_Afh)
            + ((size_t)((bm * 8 + mt) * 32 + ks * 4 + kc)) * 128 + q * 4;
        CP_ASYNC16(sb + half * 16384 + c * 16, src);
    }
    #pragma unroll
    for (int i = 0; i < 8; i++) {
        int a = t + i * 256;
        int half = a >> 10, c = a & 1023;
        int nt = c >> 6, kc = (c >> 4) & 3, q = c & 15;
        const float* src = (half ? g_Bfl : g_Bfh)
            + ((size_t)((bn * 16 + nt) * 32 + ks * 4 + kc)) * 64 + q * 4;
        CP_ASYNC16(sb + 32768 + half * 16384 + c * 16, src);
    }
}

__global__ __launch_bounds__(256, 1)
void k_gemm_mma() {
    extern __shared__ char sm_[];
    const int t = threadIdx.x, lane = t & 31, wid = t >> 5;
    const int wm = wid >> 2;         // 0..1  (m offset wm*64)
    const int wn = wid & 3;          // 0..3  (n offset wn*32)
    const int g = lane >> 2, tg = lane & 3;
    const int bn = blockIdx.x, bm = blockIdx.y;
    const int n0 = bm * 128, j0 = bn * 128;

    float* sSn = (float*)sm_;
    if (t < 128) sSn[t] = g_Snorm[j0 + t];

    copy_stage(sm_, 0, 0, bm, bn, t);
    CP_COMMIT();

    float acc[4][4][4];
    #pragma unroll
    for (int a = 0; a < 4; a++)
        #pragma unroll
        for (int b = 0; b < 4; b++)
            #pragma unroll
            for (int c = 0; c < 4; c++) acc[a][b][c] = 0.f;

    for (int ks = 0; ks < 8; ks++) {
        CP_WAIT0();
        __syncthreads();
        if (ks + 1 < 8) {
            copy_stage(sm_, (ks + 1) & 1, ks + 1, bm, bn, t);
            CP_COMMIT();
        }
        char* sbase = sm_ + 512 + (ks & 1) * STAGE_BYTES_M;
        #pragma unroll
        for (int kc = 0; kc < 4; kc++) {
            uint32_t ah[4][4], al_[4][4], bh[4][2], bl[4][2];
            #pragma unroll
            for (int j = 0; j < 4; j++) {
                uint4 x = *(const uint4*)(sbase + ((wm * 4 + j) * 4 + kc) * 512 + lane * 16);
                ah[j][0] = x.x; ah[j][1] = x.y; ah[j][2] = x.z; ah[j][3] = x.w;
                uint4 y = *(const uint4*)(sbase + 16384 + ((wm * 4 + j) * 4 + kc) * 512 + lane * 16);
                al_[j][0] = y.x; al_[j][1] = y.y; al_[j][2] = y.z; al_[j][3] = y.w;
                uint2 u = *(const uint2*)(sbase + 32768 + ((wn * 4 + j) * 4 + kc) * 256 + lane * 8);
                bh[j][0] = u.x; bh[j][1] = u.y;
                uint2 v = *(const uint2*)(sbase + 49152 + ((wn * 4 + j) * 4 + kc) * 256 + lane * 8);
                bl[j][0] = v.x; bl[j][1] = v.y;
            }
            #pragma unroll
            for (int mt = 0; mt < 4; mt++)
                #pragma unroll
                for (int nt = 0; nt < 4; nt++) {
                    mma_tf32(acc[mt][nt], ah[mt], bh[nt]);
                    mma_tf32(acc[mt][nt], ah[mt], bl[nt]);
                    mma_tf32(acc[mt][nt], al_[mt], bh[nt]);
                }
        }
    }
    __syncthreads();   // stage smem free; reuse for reduction

    float* redD = (float*)(sm_ + 512);
    int*   redJ = (int*)(sm_ + 512 + 2048);

    #pragma unroll
    for (int mt = 0; mt < 4; mt++) {
        int r0 = wm * 64 + mt * 16 + g;
        int r1 = r0 + 8;
        float an0 = g_Anorm[n0 + r0];
        float an1 = g_Anorm[n0 + r1];
        float bd0 = __int_as_float(0x7f800000), bd1 = bd0;
        int bj0 = 0, bj1 = 0;
        #pragma unroll
        for (int nt = 0; nt < 4; nt++) {
            #pragma unroll
            for (int e = 0; e < 2; e++) {
                int cl = wn * 32 + nt * 8 + tg * 2 + e;
                float sj = sSn[cl];
                int j = j0 + cl;
                float d0 = __fmaf_rn(-2.0f, acc[mt][nt][e],     __fadd_rn(an0, sj));
                float d1 = __fmaf_rn(-2.0f, acc[mt][nt][2 + e], __fadd_rn(an1, sj));
                if (d0 < bd0) { bd0 = d0; bj0 = j; }
                if (d1 < bd1) { bd1 = d1; bj1 = j; }
            }
        }
        #pragma unroll
        for (int off = 1; off <= 2; off <<= 1) {
            float d2 = __shfl_xor_sync(0xffffffffu, bd0, off);
            int   j2 = __shfl_xor_sync(0xffffffffu, bj0, off);
            if (d2 < bd0 || (d2 == bd0 && j2 < bj0)) { bd0 = d2; bj0 = j2; }
            float d3 = __shfl_xor_sync(0xffffffffu, bd1, off);
            int   j3 = __shfl_xor_sync(0xffffffffu, bj1, off);
            if (d3 < bd1 || (d3 == bd1 && j3 < bj1)) { bd1 = d3; bj1 = j3; }
        }
        if (tg == 0) {
            redD[r0 * 4 + wn] = bd0; redJ[r0 * 4 + wn] = bj0;
            redD[r1 * 4 + wn] = bd1; redJ[r1 * 4 + wn] = bj1;
        }
    }
    __syncthreads();
    if (t < 128) {
        float bd = redD[t * 4];
        int   bj = redJ[t * 4];
        #pragma unroll
        for (int w = 1; w < 4; w++) {
            float d = redD[t * 4 + w]; int j = redJ[t * 4 + w];
            if (d < bd || (d == bd && j < bj)) { bd = d; bj = j; }
        }
        int n = n0 + t;
        g_pd[(size_t)n * 32 + bn] = bd;
        g_pj[(size_t)n * 32 + bn] = bj;
    }
}

// ---------------------------------------------------------------- reduce 32 tile-partials per row
__global__ void k_finalize_argmin(float* __restrict__ out) {
    int n = blockIdx.x * 256 + threadIdx.x;
    const float* pd = g_pd + (size_t)n * 32;
    const int*   pj = g_pj + (size_t)n * 32;
    float bd = pd[0]; int bj = pj[0];
    #pragma unroll
    for (int t = 1; t < 32; t++) {
        float d = pd[t]; int j = pj[t];
        if (d < bd || (d == bd && j < bj)) { bd = d; bj = j; }
    }
    g_idx[n] = bj;
    out[OFF_IDX + n] = (float)bj;
    atomicAdd(&g_cnt[bj], 1);
}

// ---------------------------------------------------------------- one-hot scatter
__global__ void k_scatter(float* __restrict__ out) {
    int n = blockIdx.x * 256 + threadIdx.x;
    out[OFF_OH + (size_t)n * NCODE + (size_t)g_idx[n]] = 1.0f;
}

// ---------------------------------------------------------------- z_q (straight-through), z_out, loss
__global__ void k_zq_loss(const float* __restrict__ z, const float* __restrict__ E,
                          float* __restrict__ out) {
    size_t i4 = (size_t)blockIdx.x * 256 + threadIdx.x;
    size_t i = i4 * 4;
    int bb = (int)(i >> 21);
    int rem = (int)(i & 2097151u);
    int c = rem >> 13;
    int s = rem & (SPB - 1);
    float4 zp = *(const float4*)(z + i);
    int nbase = bb * SPB + s;
    float zv[4] = {zp.x, zp.y, zp.z, zp.w};
    double ls = 0.0;
    float q[4];
    #pragma unroll
    for (int u = 0; u < 4; u++) {
        int idx = g_idx[nbase + u];
        float e = E[(size_t)idx * KDIM + c];
        float d1 = __fsub_rn(e, zv[u]);
        q[u] = __fadd_rn(zv[u], d1);
        float sq = __fmul_rn(d1, d1);
        ls += (double)sq;
    }
    #pragma unroll
    for (int u = 0; u < 4; u++) {
        out[OFF_ZQ + i + u]   = q[u];
        out[OFF_ZOUT + i + u] = zv[u];
    }
    #pragma unroll
    for (int off = 16; off > 0; off >>= 1)
        ls += __shfl_down_sync(0xffffffffu, ls, off);
    __shared__ double wsum[8];
    int t = threadIdx.x;
    if ((t & 31) == 0) wsum[t >> 5] = ls;
    __syncthreads();
    if (t == 0) {
        double ssum = 0.0;
        #pragma unroll
        for (int w = 0; w < 8; w++) ssum += wsum[w];
        g_losspart[blockIdx.x] = ssum;
    }
}

// ---------------------------------------------------------------- ema update
__global__ void k_ema(const float* __restrict__ E, const float* __restrict__ ema,
                      float* __restrict__ out) {
    int i = blockIdx.x * 256 + threadIdx.x;
    float a = __fmul_rn(0.25f, ema[i]);
    float bq = __fmul_rn(0.75f, E[i]);
    out[OFF_EMA + i] = __fadd_rn(a, bq);
}

// ---------------------------------------------------------------- scalars
__global__ void k_scalars(float* __restrict__ out) {
    __shared__ double sd[256];
    int t = threadIdx.x;
    double a = 0.0;
    for (int i = t; i < 4096; i += 256) a += g_losspart[i];
    sd[t] = a;
    __syncthreads();
    for (int off = 128; off > 0; off >>= 1) {
        if (t < off) sd[t] += sd[t + off];
        __syncthreads();
    }
    if (t == 0) {
        double m = sd[0] / (double)ZTOT;
        float mf = (float)m;
        out[OFF_LOSS] = __fadd_rn(mf, __fmul_rn(0.25f, mf));
    }
    __syncthreads();
    double h = 0.0;
    for (int j = t; j < NCODE; j += 256) {
        double e = (double)g_cnt[j] / (double)NROWS;
        h += e * log(e + 1e-10);
    }
    sd[t] = h;
    __syncthreads();
    for (int off = 128; off > 0; off >>= 1) {
        if (t < off) sd[t] += sd[t + off];
        __syncthreads();
    }
    if (t == 0) out[OFF_PERP] = (float)exp(-sd[0]);
}

// ---------------------------------------------------------------- launch
extern "C" void kernel_launch(void* const* d_in, const int* in_sizes, int n_in,
                              void* d_out, int out_size) {
    const float* z   = (const float*)d_in[0];
    const float* E   = (const float*)d_in[1];
    const float* ema = (const float*)d_in[2];
    float* out = (float*)d_out;

    cudaFuncSetAttribute(k_gemm_mma, cudaFuncAttributeMaxDynamicSharedMemorySize, GSMEM);

    k_init<<<16, 256>>>();
    k_rownorm<<<NROWS / 256, 256>>>(z);
    k_codenorm<<<NCODE / 8, 256>>>(E);
    k_packA<<<4096, 256>>>(z);
    k_packB<<<2048, 256>>>(E);

    k_gemm_mma<<<dim3(NCODE / 128, NROWS / 128), 256, GSMEM>>>();

    k_finalize_argmin<<<NROWS / 256, 256>>>(out);

    cudaMemsetAsync(out + OFF_OH, 0, (size_t)NROWS * NCODE * sizeof(float), 0);
    k_scatter<<<NROWS / 256, 256>>>(out);

    k_zq_loss<<<4096, 256>>>(z, E, out);
    k_ema<<<(NCODE * KDIM) / 256, 256>>>(E, ema, out);
    k_scalars<<<1, 256>>>(out);
}

// round 11
// speedup vs baseline: 1.5497x; 1.1333x over previous
#include <cuda_runtime.h>
#include <cuda_fp16.h>
#include <math.h>
#include <stdint.h>

#define NROWS 16384      // 2 * 8*32*32
#define NCODE 4096
#define KDIM  256
#define SPB   8192       // spatial per batch
#define ZTOT  4194304    // 2*256*8192

// output layout: concatenation of reference outputs, float32
#define OFF_LOSS   0ull
#define OFF_ZQ     1ull
#define OFF_PERP   4194305ull
#define OFF_OH     4194306ull
#define OFF_IDX    71303170ull
#define OFF_ZOUT   71319554ull
#define OFF_EMA    75513858ull

// B operand pre-scale: 2^12 (exact). Descale folded into epilogue FMA as 2^-11 = 2 * 2^-12.
#define BSCALE 4096.0f

// ---------------- scratch ----------------
__device__ float  g_Anorm[NROWS];
__device__ float  g_Snorm[NCODE];
__device__ float  g_pd[NROWS * 32];
__device__ int    g_pj[NROWS * 32];
__device__ int    g_idx[NROWS];
__device__ int    g_cnt[NCODE];
__device__ double g_losspart[4096];

// fp16-split operands packed in mma.m16n8k16 fragment order (half2 per reg).
// A: [mtile 0..1023][kc16 0..15][lane 0..31][4 regs]
// B: [ntile 0..511 ][kc16 0..15][lane 0..31][2 regs]   (scaled by BSCALE)
__device__ __align__(16) uint32_t g_Afh[(size_t)1024 * 16 * 32 * 4];
__device__ __align__(16) uint32_t g_Afl[(size_t)1024 * 16 * 32 * 4];
__device__ __align__(16) uint32_t g_Bfh[(size_t)512 * 16 * 32 * 2];
__device__ __align__(16) uint32_t g_Bfl[(size_t)512 * 16 * 32 * 2];

// ---------------- helpers ----------------
__device__ __forceinline__ uint32_t smem_u32(const void* p) {
    uint32_t a;
    asm("{ .reg .u64 t; cvta.to.shared.u64 t, %1; cvt.u32.u64 %0, t; }" : "=r"(a) : "l"(p));
    return a;
}
#define CP_ASYNC16(dst, src) \
    asm volatile("cp.async.cg.shared.global [%0], [%1], 16;" :: "r"(dst), "l"(src) : "memory")
#define CP_COMMIT() asm volatile("cp.async.commit_group;" ::: "memory")
#define CP_WAIT0()  asm volatile("cp.async.wait_group 0;" ::: "memory")

__device__ __forceinline__ void mma_f16(float* c, const uint32_t* a, const uint32_t* b) {
    asm volatile("mma.sync.aligned.m16n8k16.row.col.f32.f16.f16.f32 "
        "{%0,%1,%2,%3}, {%4,%5,%6,%7}, {%8,%9}, {%0,%1,%2,%3};"
        : "+f"(c[0]), "+f"(c[1]), "+f"(c[2]), "+f"(c[3])
        : "r"(a[0]), "r"(a[1]), "r"(a[2]), "r"(a[3]), "r"(b[0]), "r"(b[1]));
}

// split one float into fp16 hi + fp16(lo) ; returns packed pair for (x,y)
__device__ __forceinline__ void split2(float x, float y, uint32_t& hi, uint32_t& lo) {
    __half hx = __float2half_rn(x), hy = __float2half_rn(y);
    float rx = __fsub_rn(x, __half2float(hx));
    float ry = __fsub_rn(y, __half2float(hy));
    __half2 h = __halves2half2(hx, hy);
    __half2 l = __halves2half2(__float2half_rn(rx), __float2half_rn(ry));
    hi = *(uint32_t*)&h;
    lo = *(uint32_t*)&l;
}

// ---------------------------------------------------------------- init
__global__ void k_init() {
    int t = blockIdx.x * 256 + threadIdx.x;
    if (t < NCODE) g_cnt[t] = 0;
}

// ---------------------------------------------------------------- row norms ||z_n||^2
__global__ void k_rownorm(const float* __restrict__ z) {
    int n = blockIdx.x * 256 + threadIdx.x;
    int b = n >> 13, s = n & (SPB - 1);
    const float* p = z + (size_t)b * (KDIM * SPB) + s;
    float a = 0.f;
    #pragma unroll 8
    for (int c = 0; c < KDIM; c++) {
        float v = p[(size_t)c * SPB];
        a = __fmaf_rn(v, v, a);
    }
    g_Anorm[n] = a;
}

// ---------------------------------------------------------------- code norms ||e_j||^2
__global__ void k_codenorm(const float* __restrict__ E) {
    int w = blockIdx.x * 8 + (threadIdx.x >> 5);
    int lane = threadIdx.x & 31;
    const float* p = E + (size_t)w * KDIM;
    float a = 0.f;
    #pragma unroll
    for (int i = 0; i < 8; i++) {
        float v = p[lane + i * 32];
        a = __fmaf_rn(v, v, a);
    }
    #pragma unroll
    for (int off = 16; off > 0; off >>= 1)
        a += __shfl_xor_sync(0xffffffffu, a, off);
    if (lane == 0) g_Snorm[w] = a;
}

// ---------------------------------------------------------------- A fragment pack
// thread -> (T mtile, kc16, lane): a0:(g,k0:k0+1) a1:(g+8,k0:k0+1) a2:(g,k0+8:+9) a3:(g+8,k0+8:+9)
__global__ void k_packA(const float* __restrict__ z) {
    int tid = blockIdx.x * 256 + threadIdx.x;   // 524,288
    int l  = tid & 31;
    int kc = (tid >> 5) & 15;
    int T  = tid >> 9;                           // 0..1023
    int g = l >> 2, tg = l & 3;
    int m = T * 16;
    int b = m >> 13;
    int s = (m & (SPB - 1)) + g;
    int k0 = kc * 16 + tg * 2;
    const float* zb = z + ((size_t)b * KDIM * SPB);
    float v00 = zb[(size_t)k0 * SPB + s];
    float v01 = zb[(size_t)(k0 + 1) * SPB + s];
    float v10 = zb[(size_t)k0 * SPB + s + 8];
    float v11 = zb[(size_t)(k0 + 1) * SPB + s + 8];
    float v02 = zb[(size_t)(k0 + 8) * SPB + s];
    float v03 = zb[(size_t)(k0 + 9) * SPB + s];
    float v12 = zb[(size_t)(k0 + 8) * SPB + s + 8];
    float v13 = zb[(size_t)(k0 + 9) * SPB + s + 8];
    uint4 hi, lo;
    split2(v00, v01, hi.x, lo.x);
    split2(v10, v11, hi.y, lo.y);
    split2(v02, v03, hi.z, lo.z);
    split2(v12, v13, hi.w, lo.w);
    size_t o = ((size_t)T * 16 + kc) * 128 + l * 4;
    *(uint4*)&g_Afh[o] = hi;
    *(uint4*)&g_Afl[o] = lo;
}

// ---------------------------------------------------------------- B fragment pack (scaled by BSCALE)
// b0:(k0:k0+1, n=g)  b1:(k0+8:k0+9, n=g)
__global__ void k_packB(const float* __restrict__ E) {
    int tid = blockIdx.x * 256 + threadIdx.x;   // 262,144
    int l  = tid & 31;
    int kc = (tid >> 5) & 15;
    int nt = tid >> 9;                           // 0..511
    int g = l >> 2, tg = l & 3;
    int n = nt * 8 + g;
    int k0 = kc * 16 + tg * 2;
    float v0 = E[(size_t)n * KDIM + k0] * BSCALE;       // exact: power-of-two scale
    float v1 = E[(size_t)n * KDIM + k0 + 1] * BSCALE;
    float v2 = E[(size_t)n * KDIM + k0 + 8] * BSCALE;
    float v3 = E[(size_t)n * KDIM + k0 + 9] * BSCALE;
    uint32_t h0, l0, h1, l1;
    split2(v0, v1, h0, l0);
    split2(v2, v3, h1, l1);
    size_t o = ((size_t)nt * 16 + kc) * 64 + l * 2;
    g_Bfh[o]     = h0;
    g_Bfh[o + 1] = h1;
    g_Bfl[o]     = l0;
    g_Bfl[o + 1] = l1;
}

// ---------------------------------------------------------------- mma GEMM + argmin
// block tile 128x128, stage = k32 (2 k16-chunks), double buffered.
// stage layout: Ahi[2kc][8mt][32lane][16B] 8K | Alo 8K | Bhi[2kc][16nt][32lane][8B] 8K | Blo 8K
#define STG 32768
#define GSMEM (512 + 2 * STG)

__device__ __forceinline__ void copy_stage(char* sm_, int st, int ks, int bm, int bn, int t) {
    uint32_t sb = smem_u32(sm_ + 512 + st * STG);
    #pragma unroll
    for (int i = 0; i < 4; i++) {          // A: 1024 chunks of 16B
        int a = t + i * 256;
        int half = a >> 9, c = a & 511;
        int kc = c >> 8, mt = (c >> 5) & 7, lane = c & 31;
        const uint32_t* src = (half ? g_Afl : g_Afh)
            + (((size_t)(bm * 8 + mt) * 16 + ks * 2 + kc) * 32 + lane) * 4;
        CP_ASYNC16(sb + half * 8192 + c * 16, src);
    }
    #pragma unroll
    for (int i = 0; i < 4; i++) {          // B: 1024 chunks of 16B (2 lanes each)
        int a = t + i * 256;
        int half = a >> 9, c = a & 511;
        int u = c * 2;
        int kc = u >> 9, nt = (u >> 5) & 15, lane = u & 31;
        const uint32_t* src = (half ? g_Bfl : g_Bfh)
            + (((size_t)(bn * 16 + nt) * 16 + ks * 2 + kc) * 32 + lane) * 2;
        CP_ASYNC16(sb + 16384 + half * 8192 + c * 16, src);
    }
}

__global__ __launch_bounds__(256, 1)
void k_gemm_mma() {
    extern __shared__ char sm_[];
    const int t = threadIdx.x, lane = t & 31, wid = t >> 5;
    const int wm = wid >> 2;         // 0..1  (m offset wm*64)
    const int wn = wid & 3;          // 0..3  (n offset wn*32)
    const int g = lane >> 2, tg = lane & 3;
    const int bn = blockIdx.x, bm = blockIdx.y;
    const int n0 = bm * 128, j0 = bn * 128;

    float* sSn = (float*)sm_;
    if (t < 128) sSn[t] = g_Snorm[j0 + t];

    copy_stage(sm_, 0, 0, bm, bn, t);
    CP_COMMIT();

    float acc[4][4][4];
    #pragma unroll
    for (int a = 0; a < 4; a++)
        #pragma unroll
        for (int b = 0; b < 4; b++)
            #pragma unroll
            for (int c = 0; c < 4; c++) acc[a][b][c] = 0.f;

    for (int ks = 0; ks < 8; ks++) {
        CP_WAIT0();
        __syncthreads();
        if (ks + 1 < 8) {
            copy_stage(sm_, (ks + 1) & 1, ks + 1, bm, bn, t);
            CP_COMMIT();
        }
        char* sbase = sm_ + 512 + (ks & 1) * STG;
        #pragma unroll
        for (int kc = 0; kc < 2; kc++) {
            uint32_t ah[4][4], al_[4][4], bh[4][2], bl[4][2];
            #pragma unroll
            for (int j = 0; j < 4; j++) {
                uint4 x = *(const uint4*)(sbase + ((kc * 8 + wm * 4 + j) * 32 + lane) * 16);
                ah[j][0] = x.x; ah[j][1] = x.y; ah[j][2] = x.z; ah[j][3] = x.w;
                uint4 y = *(const uint4*)(sbase + 8192 + ((kc * 8 + wm * 4 + j) * 32 + lane) * 16);
                al_[j][0] = y.x; al_[j][1] = y.y; al_[j][2] = y.z; al_[j][3] = y.w;
                uint2 u = *(const uint2*)(sbase + 16384 + ((kc * 16 + wn * 4 + j) * 32 + lane) * 8);
                bh[j][0] = u.x; bh[j][1] = u.y;
                uint2 v = *(const uint2*)(sbase + 24576 + ((kc * 16 + wn * 4 + j) * 32 + lane) * 8);
                bl[j][0] = v.x; bl[j][1] = v.y;
            }
            #pragma unroll
            for (int mt = 0; mt < 4; mt++)
                #pragma unroll
                for (int nt = 0; nt < 4; nt++) {
                    mma_f16(acc[mt][nt], ah[mt], bh[nt]);
                    mma_f16(acc[mt][nt], ah[mt], bl[nt]);
                    mma_f16(acc[mt][nt], al_[mt], bh[nt]);
                }
        }
    }
    __syncthreads();   // stage smem free; reuse for reduction

    float* redD = (float*)(sm_ + 512);
    int*   redJ = (int*)(sm_ + 512 + 2048);

    // d = fl( fl(An+Sj) - 2 * (acc * 2^-12) ) ; descale folded: fmaf(-2^-11, acc, t) (exact)
    #pragma unroll
    for (int mt = 0; mt < 4; mt++) {
        int r0 = wm * 64 + mt * 16 + g;
        int r1 = r0 + 8;
        float an0 = g_Anorm[n0 + r0];
        float an1 = g_Anorm[n0 + r1];
        float bd0 = __int_as_float(0x7f800000), bd1 = bd0;
        int bj0 = 0, bj1 = 0;
        #pragma unroll
        for (int nt = 0; nt < 4; nt++) {
            #pragma unroll
            for (int e = 0; e < 2; e++) {
                int cl = wn * 32 + nt * 8 + tg * 2 + e;
                float sj = sSn[cl];
                int j = j0 + cl;
                float d0 = __fmaf_rn(-0x1p-11f, acc[mt][nt][e],     __fadd_rn(an0, sj));
                float d1 = __fmaf_rn(-0x1p-11f, acc[mt][nt][2 + e], __fadd_rn(an1, sj));
                if (d0 < bd0) { bd0 = d0; bj0 = j; }
                if (d1 < bd1) { bd1 = d1; bj1 = j; }
            }
        }
        #pragma unroll
        for (int off = 1; off <= 2; off <<= 1) {
            float d2 = __shfl_xor_sync(0xffffffffu, bd0, off);
            int   j2 = __shfl_xor_sync(0xffffffffu, bj0, off);
            if (d2 < bd0 || (d2 == bd0 && j2 < bj0)) { bd0 = d2; bj0 = j2; }
            float d3 = __shfl_xor_sync(0xffffffffu, bd1, off);
            int   j3 = __shfl_xor_sync(0xffffffffu, bj1, off);
            if (d3 < bd1 || (d3 == bd1 && j3 < bj1)) { bd1 = d3; bj1 = j3; }
        }
        if (tg == 0) {
            redD[r0 * 4 + wn] = bd0; redJ[r0 * 4 + wn] = bj0;
            redD[r1 * 4 + wn] = bd1; redJ[r1 * 4 + wn] = bj1;
        }
    }
    __syncthreads();
    if (t < 128) {
        float bd = redD[t * 4];
        int   bj = redJ[t * 4];
        #pragma unroll
        for (int w = 1; w < 4; w++) {
            float d = redD[t * 4 + w]; int j = redJ[t * 4 + w];
            if (d < bd || (d == bd && j < bj)) { bd = d; bj = j; }
        }
        int n = n0 + t;
        g_pd[(size_t)n * 32 + bn] = bd;
        g_pj[(size_t)n * 32 + bn] = bj;
    }
}

// ---------------------------------------------------------------- reduce 32 tile-partials per row
__global__ void k_finalize_argmin(float* __restrict__ out) {
    int n = blockIdx.x * 256 + threadIdx.x;
    const float* pd = g_pd + (size_t)n * 32;
    const int*   pj = g_pj + (size_t)n * 32;
    float bd = pd[0]; int bj = pj[0];
    #pragma unroll
    for (int t = 1; t < 32; t++) {
        float d = pd[t]; int j = pj[t];
        if (d < bd || (d == bd && j < bj)) { bd = d; bj = j; }
    }
    g_idx[n] = bj;
    out[OFF_IDX + n] = (float)bj;
    atomicAdd(&g_cnt[bj], 1);
}

// ---------------------------------------------------------------- one-hot rows (zeros + the 1), float2 stores
__global__ void k_onehot(float* __restrict__ out) {
    int row = blockIdx.x;
    int t = threadIdx.x;                  // 128 threads, 16 float2 each
    int idx = g_idx[row];
    float2* dst = (float2*)(out + OFF_OH + (size_t)row * NCODE);
    #pragma unroll
    for (int i = 0; i < 16; i++) {
        int p = t * 16 + i;               // float2 slot 0..2047
        float2 v = make_float2(0.f, 0.f);
        if ((idx >> 1) == p) ((idx & 1) ? v.y : v.x) = 1.0f;
        dst[p] = v;
    }
}

// ---------------------------------------------------------------- z_q (straight-through), z_out, loss
__global__ void k_zq_loss(const float* __restrict__ z, const float* __restrict__ E,
                          float* __restrict__ out) {
    size_t i4 = (size_t)blockIdx.x * 256 + threadIdx.x;
    size_t i = i4 * 4;
    int bb = (int)(i >> 21);
    int rem = (int)(i & 2097151u);
    int c = rem >> 13;
    int s = rem & (SPB - 1);
    float4 zp = *(const float4*)(z + i);
    int nbase = bb * SPB + s;
    float zv[4] = {zp.x, zp.y, zp.z, zp.w};
    double ls = 0.0;
    float q[4];
    #pragma unroll
    for (int u = 0; u < 4; u++) {
        int idx = g_idx[nbase + u];
        float e = E[(size_t)idx * KDIM + c];
        float d1 = __fsub_rn(e, zv[u]);
        q[u] = __fadd_rn(zv[u], d1);
        float sq = __fmul_rn(d1, d1);
        ls += (double)sq;
    }
    #pragma unroll
    for (int u = 0; u < 4; u++) {
        out[OFF_ZQ + i + u]   = q[u];
        out[OFF_ZOUT + i + u] = zv[u];
    }
    #pragma unroll
    for (int off = 16; off > 0; off >>= 1)
        ls += __shfl_down_sync(0xffffffffu, ls, off);
    __shared__ double wsum[8];
    int t = threadIdx.x;
    if ((t & 31) == 0) wsum[t >> 5] = ls;
    __syncthreads();
    if (t == 0) {
        double ssum = 0.0;
        #pragma unroll
        for (int w = 0; w < 8; w++) ssum += wsum[w];
        g_losspart[blockIdx.x] = ssum;
    }
}

// ---------------------------------------------------------------- ema update
__global__ void k_ema(const float* __restrict__ E, const float* __restrict__ ema,
                      float* __restrict__ out) {
    int i = blockIdx.x * 256 + threadIdx.x;
    float a = __fmul_rn(0.25f, ema[i]);
    float bq = __fmul_rn(0.75f, E[i]);
    out[OFF_EMA + i] = __fadd_rn(a, bq);
}

// ---------------------------------------------------------------- scalars
__global__ void k_scalars(float* __restrict__ out) {
    __shared__ double sd[256];
    int t = threadIdx.x;
    double a = 0.0;
    for (int i = t; i < 4096; i += 256) a += g_losspart[i];
    sd[t] = a;
    __syncthreads();
    for (int off = 128; off > 0; off >>= 1) {
        if (t < off) sd[t] += sd[t + off];
        __syncthreads();
    }
    if (t == 0) {
        double m = sd[0] / (double)ZTOT;
        float mf = (float)m;
        out[OFF_LOSS] = __fadd_rn(mf, __fmul_rn(0.25f, mf));
    }
    __syncthreads();
    double h = 0.0;
    for (int j = t; j < NCODE; j += 256) {
        double e = (double)g_cnt[j] / (double)NROWS;
        h += e * log(e + 1e-10);
    }
    sd[t] = h;
    __syncthreads();
    for (int off = 128; off > 0; off >>= 1) {
        if (t < off) sd[t] += sd[t + off];
        __syncthreads();
    }
    if (t == 0) out[OFF_PERP] = (float)exp(-sd[0]);
}

// ---------------------------------------------------------------- launch
extern "C" void kernel_launch(void* const* d_in, const int* in_sizes, int n_in,
                              void* d_out, int out_size) {
    const float* z   = (const float*)d_in[0];
    const float* E   = (const float*)d_in[1];
    const float* ema = (const float*)d_in[2];
    float* out = (float*)d_out;

    cudaFuncSetAttribute(k_gemm_mma, cudaFuncAttributeMaxDynamicSharedMemorySize, GSMEM);

    k_init<<<16, 256>>>();
    k_rownorm<<<NROWS / 256, 256>>>(z);
    k_codenorm<<<NCODE / 8, 256>>>(E);
    k_packA<<<2048, 256>>>(z);
    k_packB<<<1024, 256>>>(E);

    k_gemm_mma<<<dim3(NCODE / 128, NROWS / 128), 256, GSMEM>>>();

    k_finalize_argmin<<<NROWS / 256, 256>>>(out);
    k_onehot<<<NROWS, 128>>>(out);

    k_zq_loss<<<4096, 256>>>(z, E, out);
    k_ema<<<(NCODE * KDIM) / 256, 256>>>(E, ema, out);
    k_scalars<<<1, 256>>>(out);
}

// round 12
// speedup vs baseline: 1.5633x; 1.0088x over previous
#include <cuda_runtime.h>
#include <cuda_fp16.h>
#include <math.h>
#include <stdint.h>

#define NROWS 16384      // 2 * 8*32*32
#define NCODE 4096
#define KDIM  256
#define SPB   8192       // spatial per batch
#define ZTOT  4194304    // 2*256*8192

// output layout: concatenation of reference outputs, float32
#define OFF_LOSS   0ull
#define OFF_ZQ     1ull
#define OFF_PERP   4194305ull
#define OFF_OH     4194306ull
#define OFF_IDX    71303170ull
#define OFF_ZOUT   71319554ull
#define OFF_EMA    75513858ull

// B operand pre-scale: 2^12 (exact). Descale folded into epilogue FMA as 2^-11 = 2 * 2^-12.
#define BSCALE 4096.0f

// ---------------- scratch ----------------
__device__ float  g_Anorm[NROWS];
__device__ float  g_Snorm[NCODE];
__device__ float  g_pd[NROWS * 32];
__device__ int    g_pj[NROWS * 32];
__device__ int    g_idx[NROWS];
__device__ int    g_cnt[NCODE];
__device__ double g_losspart[4096];

// fp16-split operands packed in mma.m16n8k16 fragment order (half2 per reg).
// A: [mtile 0..1023][kc16 0..15][lane 0..31][4 regs]
// B: [ntile 0..511 ][kc16 0..15][lane 0..31][2 regs]   (scaled by BSCALE)
__device__ __align__(16) uint32_t g_Afh[(size_t)1024 * 16 * 32 * 4];
__device__ __align__(16) uint32_t g_Afl[(size_t)1024 * 16 * 32 * 4];
__device__ __align__(16) uint32_t g_Bfh[(size_t)512 * 16 * 32 * 2];
__device__ __align__(16) uint32_t g_Bfl[(size_t)512 * 16 * 32 * 2];

// ---------------- helpers ----------------
__device__ __forceinline__ uint32_t smem_u32(const void* p) {
    uint32_t a;
    asm("{ .reg .u64 t; cvta.to.shared.u64 t, %1; cvt.u32.u64 %0, t; }" : "=r"(a) : "l"(p));
    return a;
}
#define CP_ASYNC16(dst, src) \
    asm volatile("cp.async.cg.shared.global [%0], [%1], 16;" :: "r"(dst), "l"(src) : "memory")
#define CP_COMMIT() asm volatile("cp.async.commit_group;" ::: "memory")
#define CP_WAIT0()  asm volatile("cp.async.wait_group 0;" ::: "memory")

__device__ __forceinline__ void mma_f16(float* c, const uint32_t* a, const uint32_t* b) {
    asm volatile("mma.sync.aligned.m16n8k16.row.col.f32.f16.f16.f32 "
        "{%0,%1,%2,%3}, {%4,%5,%6,%7}, {%8,%9}, {%0,%1,%2,%3};"
        : "+f"(c[0]), "+f"(c[1]), "+f"(c[2]), "+f"(c[3])
        : "r"(a[0]), "r"(a[1]), "r"(a[2]), "r"(a[3]), "r"(b[0]), "r"(b[1]));
}

// split one float into fp16 hi + fp16(lo) ; returns packed pair for (x,y)
__device__ __forceinline__ void split2(float x, float y, uint32_t& hi, uint32_t& lo) {
    __half hx = __float2half_rn(x), hy = __float2half_rn(y);
    float rx = __fsub_rn(x, __half2float(hx));
    float ry = __fsub_rn(y, __half2float(hy));
    __half2 h = __halves2half2(hx, hy);
    __half2 l = __halves2half2(__float2half_rn(rx), __float2half_rn(ry));
    hi = *(uint32_t*)&h;
    lo = *(uint32_t*)&l;
}

// ---------------------------------------------------------------- init
__global__ void k_init() {
    int t = blockIdx.x * 256 + threadIdx.x;
    if (t < NCODE) g_cnt[t] = 0;
}

// ---------------------------------------------------------------- row norms ||z_n||^2
__global__ void k_rownorm(const float* __restrict__ z) {
    int n = blockIdx.x * 256 + threadIdx.x;
    int b = n >> 13, s = n & (SPB - 1);
    const float* p = z + (size_t)b * (KDIM * SPB) + s;
    float a = 0.f;
    #pragma unroll 8
    for (int c = 0; c < KDIM; c++) {
        float v = p[(size_t)c * SPB];
        a = __fmaf_rn(v, v, a);
    }
    g_Anorm[n] = a;
}

// ---------------------------------------------------------------- code norms ||e_j||^2
__global__ void k_codenorm(const float* __restrict__ E) {
    int w = blockIdx.x * 8 + (threadIdx.x >> 5);
    int lane = threadIdx.x & 31;
    const float* p = E + (size_t)w * KDIM;
    float a = 0.f;
    #pragma unroll
    for (int i = 0; i < 8; i++) {
        float v = p[lane + i * 32];
        a = __fmaf_rn(v, v, a);
    }
    #pragma unroll
    for (int off = 16; off > 0; off >>= 1)
        a += __shfl_xor_sync(0xffffffffu, a, off);
    if (lane == 0) g_Snorm[w] = a;
}

// ---------------------------------------------------------------- A fragment pack
// thread -> (T mtile, kc16, lane): a0:(g,k0:k0+1) a1:(g+8,k0:k0+1) a2:(g,k0+8:+9) a3:(g+8,k0+8:+9)
__global__ void k_packA(const float* __restrict__ z) {
    int tid = blockIdx.x * 256 + threadIdx.x;   // 524,288
    int l  = tid & 31;
    int kc = (tid >> 5) & 15;
    int T  = tid >> 9;                           // 0..1023
    int g = l >> 2, tg = l & 3;
    int m = T * 16;
    int b = m >> 13;
    int s = (m & (SPB - 1)) + g;
    int k0 = kc * 16 + tg * 2;
    const float* zb = z + ((size_t)b * KDIM * SPB);
    float v00 = zb[(size_t)k0 * SPB + s];
    float v01 = zb[(size_t)(k0 + 1) * SPB + s];
    float v10 = zb[(size_t)k0 * SPB + s + 8];
    float v11 = zb[(size_t)(k0 + 1) * SPB + s + 8];
    float v02 = zb[(size_t)(k0 + 8) * SPB + s];
    float v03 = zb[(size_t)(k0 + 9) * SPB + s];
    float v12 = zb[(size_t)(k0 + 8) * SPB + s + 8];
    float v13 = zb[(size_t)(k0 + 9) * SPB + s + 8];
    uint4 hi, lo;
    split2(v00, v01, hi.x, lo.x);
    split2(v10, v11, hi.y, lo.y);
    split2(v02, v03, hi.z, lo.z);
    split2(v12, v13, hi.w, lo.w);
    size_t o = ((size_t)T * 16 + kc) * 128 + l * 4;
    *(uint4*)&g_Afh[o] = hi;
    *(uint4*)&g_Afl[o] = lo;
}

// ---------------------------------------------------------------- B fragment pack (scaled by BSCALE)
// b0:(k0:k0+1, n=g)  b1:(k0+8:k0+9, n=g)
__global__ void k_packB(const float* __restrict__ E) {
    int tid = blockIdx.x * 256 + threadIdx.x;   // 262,144
    int l  = tid & 31;
    int kc = (tid >> 5) & 15;
    int nt = tid >> 9;                           // 0..511
    int g = l >> 2, tg = l & 3;
    int n = nt * 8 + g;
    int k0 = kc * 16 + tg * 2;
    float v0 = E[(size_t)n * KDIM + k0] * BSCALE;       // exact: power-of-two scale
    float v1 = E[(size_t)n * KDIM + k0 + 1] * BSCALE;
    float v2 = E[(size_t)n * KDIM + k0 + 8] * BSCALE;
    float v3 = E[(size_t)n * KDIM + k0 + 9] * BSCALE;
    uint32_t h0, l0, h1, l1;
    split2(v0, v1, h0, l0);
    split2(v2, v3, h1, l1);
    size_t o = ((size_t)nt * 16 + kc) * 64 + l * 2;
    g_Bfh[o]     = h0;
    g_Bfh[o + 1] = h1;
    g_Bfl[o]     = l0;
    g_Bfl[o + 1] = l1;
}

// ---------------------------------------------------------------- mma GEMM + argmin
// block tile 128x128, stage = k32 (2 k16-chunks), double buffered.
// stage layout: Ahi[2kc][8mt][32lane][16B] 8K | Alo 8K | Bhi[2kc][16nt][32lane][8B] 8K | Blo 8K
#define STG 32768
#define GSMEM (512 + 2 * STG)

__device__ __forceinline__ void copy_stage(char* sm_, int st, int ks, int bm, int bn, int t) {
    uint32_t sb = smem_u32(sm_ + 512 + st * STG);
    #pragma unroll
    for (int i = 0; i < 4; i++) {          // A: 1024 chunks of 16B
        int a = t + i * 256;
        int half = a >> 9, c = a & 511;
        int kc = c >> 8, mt = (c >> 5) & 7, lane = c & 31;
        const uint32_t* src = (half ? g_Afl : g_Afh)
            + (((size_t)(bm * 8 + mt) * 16 + ks * 2 + kc) * 32 + lane) * 4;
        CP_ASYNC16(sb + half * 8192 + c * 16, src);
    }
    #pragma unroll
    for (int i = 0; i < 4; i++) {          // B: 1024 chunks of 16B (2 lanes each)
        int a = t + i * 256;
        int half = a >> 9, c = a & 511;
        int u = c * 2;
        int kc = u >> 9, nt = (u >> 5) & 15, lane = u & 31;
        const uint32_t* src = (half ? g_Bfl : g_Bfh)
            + (((size_t)(bn * 16 + nt) * 16 + ks * 2 + kc) * 32 + lane) * 2;
        CP_ASYNC16(sb + 16384 + half * 8192 + c * 16, src);
    }
}

__global__ __launch_bounds__(256, 1)
void k_gemm_mma() {
    extern __shared__ char sm_[];
    const int t = threadIdx.x, lane = t & 31, wid = t >> 5;
    const int wm = wid >> 2;         // 0..1  (m offset wm*64)
    const int wn = wid & 3;          // 0..3  (n offset wn*32)
    const int g = lane >> 2, tg = lane & 3;
    const int bn = blockIdx.x, bm = blockIdx.y;
    const int n0 = bm * 128, j0 = bn * 128;

    float* sSn = (float*)sm_;
    if (t < 128) sSn[t] = g_Snorm[j0 + t];

    copy_stage(sm_, 0, 0, bm, bn, t);
    CP_COMMIT();

    float acc[4][4][4];
    #pragma unroll
    for (int a = 0; a < 4; a++)
        #pragma unroll
        for (int b = 0; b < 4; b++)
            #pragma unroll
            for (int c = 0; c < 4; c++) acc[a][b][c] = 0.f;

    for (int ks = 0; ks < 8; ks++) {
        CP_WAIT0();
        __syncthreads();
        if (ks + 1 < 8) {
            copy_stage(sm_, (ks + 1) & 1, ks + 1, bm, bn, t);
            CP_COMMIT();
        }
        char* sbase = sm_ + 512 + (ks & 1) * STG;
        #pragma unroll
        for (int kc = 0; kc < 2; kc++) {
            uint32_t ah[4][4], al_[4][4], bh[4][2], bl[4][2];
            #pragma unroll
            for (int j = 0; j < 4; j++) {
                uint4 x = *(const uint4*)(sbase + ((kc * 8 + wm * 4 + j) * 32 + lane) * 16);
                ah[j][0] = x.x; ah[j][1] = x.y; ah[j][2] = x.z; ah[j][3] = x.w;
                uint4 y = *(const uint4*)(sbase + 8192 + ((kc * 8 + wm * 4 + j) * 32 + lane) * 16);
                al_[j][0] = y.x; al_[j][1] = y.y; al_[j][2] = y.z; al_[j][3] = y.w;
                uint2 u = *(const uint2*)(sbase + 16384 + ((kc * 16 + wn * 4 + j) * 32 + lane) * 8);
                bh[j][0] = u.x; bh[j][1] = u.y;
                uint2 v = *(const uint2*)(sbase + 24576 + ((kc * 16 + wn * 4 + j) * 32 + lane) * 8);
                bl[j][0] = v.x; bl[j][1] = v.y;
            }
            // Pass-major ordering: 16 independent mmas between successive writes to
            // any accumulator (breaks the RAW chain), while each accumulator still
            // receives hh -> hl -> lh in the same order (bit-exact vs tile-major).
            #pragma unroll
            for (int mt = 0; mt < 4; mt++)
                #pragma unroll
                for (int nt = 0; nt < 4; nt++)
                    mma_f16(acc[mt][nt], ah[mt], bh[nt]);
            #pragma unroll
            for (int mt = 0; mt < 4; mt++)
                #pragma unroll
                for (int nt = 0; nt < 4; nt++)
                    mma_f16(acc[mt][nt], ah[mt], bl[nt]);
            #pragma unroll
            for (int mt = 0; mt < 4; mt++)
                #pragma unroll
                for (int nt = 0; nt < 4; nt++)
                    mma_f16(acc[mt][nt], al_[mt], bh[nt]);
        }
    }
    __syncthreads();   // stage smem free; reuse for reduction

    float* redD = (float*)(sm_ + 512);
    int*   redJ = (int*)(sm_ + 512 + 2048);

    // d = fl( fl(An+Sj) - 2 * (acc * 2^-12) ) ; descale folded: fmaf(-2^-11, acc, t) (exact)
    #pragma unroll
    for (int mt = 0; mt < 4; mt++) {
        int r0 = wm * 64 + mt * 16 + g;
        int r1 = r0 + 8;
        float an0 = g_Anorm[n0 + r0];
        float an1 = g_Anorm[n0 + r1];
        float bd0 = __int_as_float(0x7f800000), bd1 = bd0;
        int bj0 = 0, bj1 = 0;
        #pragma unroll
        for (int nt = 0; nt < 4; nt++) {
            #pragma unroll
            for (int e = 0; e < 2; e++) {
                int cl = wn * 32 + nt * 8 + tg * 2 + e;
                float sj = sSn[cl];
                int j = j0 + cl;
                float d0 = __fmaf_rn(-0x1p-11f, acc[mt][nt][e],     __fadd_rn(an0, sj));
                float d1 = __fmaf_rn(-0x1p-11f, acc[mt][nt][2 + e], __fadd_rn(an1, sj));
                if (d0 < bd0) { bd0 = d0; bj0 = j; }
                if (d1 < bd1) { bd1 = d1; bj1 = j; }
            }
        }
        #pragma unroll
        for (int off = 1; off <= 2; off <<= 1) {
            float d2 = __shfl_xor_sync(0xffffffffu, bd0, off);
            int   j2 = __shfl_xor_sync(0xffffffffu, bj0, off);
            if (d2 < bd0 || (d2 == bd0 && j2 < bj0)) { bd0 = d2; bj0 = j2; }
            float d3 = __shfl_xor_sync(0xffffffffu, bd1, off);
            int   j3 = __shfl_xor_sync(0xffffffffu, bj1, off);
            if (d3 < bd1 || (d3 == bd1 && j3 < bj1)) { bd1 = d3; bj1 = j3; }
        }
        if (tg == 0) {
            redD[r0 * 4 + wn] = bd0; redJ[r0 * 4 + wn] = bj0;
            redD[r1 * 4 + wn] = bd1; redJ[r1 * 4 + wn] = bj1;
        }
    }
    __syncthreads();
    if (t < 128) {
        float bd = redD[t * 4];
        int   bj = redJ[t * 4];
        #pragma unroll
        for (int w = 1; w < 4; w++) {
            float d = redD[t * 4 + w]; int j = redJ[t * 4 + w];
            if (d < bd || (d == bd && j < bj)) { bd = d; bj = j; }
        }
        int n = n0 + t;
        g_pd[(size_t)n * 32 + bn] = bd;
        g_pj[(size_t)n * 32 + bn] = bj;
    }
}

// ---------------------------------------------------------------- reduce 32 tile-partials per row
__global__ void k_finalize_argmin(float* __restrict__ out) {
    int n = blockIdx.x * 256 + threadIdx.x;
    const float* pd = g_pd + (size_t)n * 32;
    const int*   pj = g_pj + (size_t)n * 32;
    float bd = pd[0]; int bj = pj[0];
    #pragma unroll
    for (int t = 1; t < 32; t++) {
        float d = pd[t]; int j = pj[t];
        if (d < bd || (d == bd && j < bj)) { bd = d; bj = j; }
    }
    g_idx[n] = bj;
    out[OFF_IDX + n] = (float)bj;
    atomicAdd(&g_cnt[bj], 1);
}

// ---------------------------------------------------------------- one-hot rows (zeros + the 1), float2 stores
__global__ void k_onehot(float* __restrict__ out) {
    int row = blockIdx.x;
    int t = threadIdx.x;                  // 128 threads, 16 float2 each
    int idx = g_idx[row];
    float2* dst = (float2*)(out + OFF_OH + (size_t)row * NCODE);
    #pragma unroll
    for (int i = 0; i < 16; i++) {
        int p = t * 16 + i;               // float2 slot 0..2047
        float2 v = make_float2(0.f, 0.f);
        if ((idx >> 1) == p) ((idx & 1) ? v.y : v.x) = 1.0f;
        dst[p] = v;
    }
}

// ---------------------------------------------------------------- z_q (straight-through), z_out, loss
__global__ void k_zq_loss(const float* __restrict__ z, const float* __restrict__ E,
                          float* __restrict__ out) {
    size_t i4 = (size_t)blockIdx.x * 256 + threadIdx.x;
    size_t i = i4 * 4;
    int bb = (int)(i >> 21);
    int rem = (int)(i & 2097151u);
    int c = rem >> 13;
    int s = rem & (SPB - 1);
    float4 zp = *(const float4*)(z + i);
    int nbase = bb * SPB + s;
    float zv[4] = {zp.x, zp.y, zp.z, zp.w};
    double ls = 0.0;
    float q[4];
    #pragma unroll
    for (int u = 0; u < 4; u++) {
        int idx = g_idx[nbase + u];
        float e = E[(size_t)idx * KDIM + c];
        float d1 = __fsub_rn(e, zv[u]);
        q[u] = __fadd_rn(zv[u], d1);
        float sq = __fmul_rn(d1, d1);
        ls += (double)sq;
    }
    #pragma unroll
    for (int u = 0; u < 4; u++) {
        out[OFF_ZQ + i + u]   = q[u];
        out[OFF_ZOUT + i + u] = zv[u];
    }
    #pragma unroll
    for (int off = 16; off > 0; off >>= 1)
        ls += __shfl_down_sync(0xffffffffu, ls, off);
    __shared__ double wsum[8];
    int t = threadIdx.x;
    if ((t & 31) == 0) wsum[t >> 5] = ls;
    __syncthreads();
    if (t == 0) {
        double ssum = 0.0;
        #pragma unroll
        for (int w = 0; w < 8; w++) ssum += wsum[w];
        g_losspart[blockIdx.x] = ssum;
    }
}

// ---------------------------------------------------------------- ema update
__global__ void k_ema(const float* __restrict__ E, const float* __restrict__ ema,
                      float* __restrict__ out) {
    int i = blockIdx.x * 256 + threadIdx.x;
    float a = __fmul_rn(0.25f, ema[i]);
    float bq = __fmul_rn(0.75f, E[i]);
    out[OFF_EMA + i] = __fadd_rn(a, bq);
}

// ---------------------------------------------------------------- scalars
__global__ void k_scalars(float* __restrict__ out) {
    __shared__ double sd[256];
    int t = threadIdx.x;
    double a = 0.0;
    for (int i = t; i < 4096; i += 256) a += g_losspart[i];
    sd[t] = a;
    __syncthreads();
    for (int off = 128; off > 0; off >>= 1) {
        if (t < off) sd[t] += sd[t + off];
        __syncthreads();
    }
    if (t == 0) {
        double m = sd[0] / (double)ZTOT;
        float mf = (float)m;
        out[OFF_LOSS] = __fadd_rn(mf, __fmul_rn(0.25f, mf));
    }
    __syncthreads();
    double h = 0.0;
    for (int j = t; j < NCODE; j += 256) {
        double e = (double)g_cnt[j] / (double)NROWS;
        h += e * log(e + 1e-10);
    }
    sd[t] = h;
    __syncthreads();
    for (int off = 128; off > 0; off >>= 1) {
        if (t < off) sd[t] += sd[t + off];
        __syncthreads();
    }
    if (t == 0) out[OFF_PERP] = (float)exp(-sd[0]);
}

// ---------------------------------------------------------------- launch
extern "C" void kernel_launch(void* const* d_in, const int* in_sizes, int n_in,
                              void* d_out, int out_size) {
    const float* z   = (const float*)d_in[0];
    const float* E   = (const float*)d_in[1];
    const float* ema = (const float*)d_in[2];
    float* out = (float*)d_out;

    cudaFuncSetAttribute(k_gemm_mma, cudaFuncAttributeMaxDynamicSharedMemorySize, GSMEM);

    k_init<<<16, 256>>>();
    k_rownorm<<<NROWS / 256, 256>>>(z);
    k_codenorm<<<NCODE / 8, 256>>>(E);
    k_packA<<<2048, 256>>>(z);
    k_packB<<<1024, 256>>>(E);

    k_gemm_mma<<<dim3(NCODE / 128, NROWS / 128), 256, GSMEM>>>();

    k_finalize_argmin<<<NROWS / 256, 256>>>(out);
    k_onehot<<<NROWS, 128>>>(out);

    k_zq_loss<<<4096, 256>>>(z, E, out);
    k_ema<<<(NCODE * KDIM) / 256, 256>>>(E, ema, out);
    k_scalars<<<1, 256>>>(out);
}